// round 15
// baseline (speedup 1.0000x reference)
#include <cuda_runtime.h>
#include <cuda_fp16.h>
#include <math.h>

// ---------------- problem constants ----------------
constexpr int CB   = 256;   // batch
constexpr int CTXD = 512;
constexpr int DOF  = 6;
constexpr int WSZ  = 300;
constexpr int PGD  = 256;
constexpr int PWD  = 512;
constexpr int HGD  = 256;
constexpr int HWD  = 512;
constexpr int ZD   = 306;   // DOF + WSZ
constexpr int NSTEP = 19;   // max_segments - 1
constexpr int NW   = PWD * ZD;   // 156672 = big-GEMM N

// ---------------- scratch layout (single __device__ array, no allocs) ----------
constexpr size_t OFF_TMPW = 0;                               // [b][j*512+o]
constexpr size_t SZ_TMPW  = (size_t)CB * NW;
constexpr size_t OFF_BWT  = OFF_TMPW + SZ_TMPW;              // [(j*512+o)][i]
constexpr size_t SZ_BWT   = (size_t)NW * CTXD;
constexpr size_t OFF_TMPG = OFF_BWT + SZ_BWT;
constexpr size_t SZ_TMPG  = (size_t)CB * PGD * DOF;
constexpr size_t OFF_CTXT = OFF_TMPG + SZ_TMPG;
constexpr size_t OFF_PG   = OFF_CTXT + (size_t)CTXD * CB;
constexpr size_t OFF_PW   = OFF_PG + (size_t)CB * DOF;
constexpr size_t OFF_XPRE = OFF_PW + (size_t)CB * WSZ;
constexpr size_t OFF_YPRE = OFF_XPRE + (size_t)CB * PGD;
constexpr size_t OFF_X    = OFF_YPRE + (size_t)CB * PWD;
constexpr size_t OFF_Y    = OFF_X + (size_t)CB * PGD;
// zero-init region (states used as step-1 inputs)
constexpr size_t OFF_ZERO = OFF_Y + (size_t)CB * PWD;
constexpr size_t OFF_GH0A = OFF_ZERO;
constexpr size_t OFF_GH1A = OFF_GH0A + (size_t)CB * HGD;
constexpr size_t OFF_WH0A = OFF_GH1A + (size_t)CB * HGD;
constexpr size_t OFF_WH1A = OFF_WH0A + (size_t)CB * HWD;
constexpr size_t OFF_GC0  = OFF_WH1A + (size_t)CB * HWD;
constexpr size_t OFF_GC1  = OFF_GC0 + (size_t)CB * HGD;
constexpr size_t OFF_WC0  = OFF_GC1 + (size_t)CB * HGD;
constexpr size_t OFF_WC1  = OFF_WC0 + (size_t)CB * HWD;
constexpr size_t SZ_ZERO  = OFF_WC1 + (size_t)CB * HWD - OFF_ZERO;
// double-buffer "B" halves (not zeroed)
constexpr size_t OFF_GH0B = OFF_WC1 + (size_t)CB * HWD;
constexpr size_t OFF_GH1B = OFF_GH0B + (size_t)CB * HGD;
constexpr size_t OFF_WH0B = OFF_GH1B + (size_t)CB * HGD;
constexpr size_t OFF_WH1B = OFF_WH0B + (size_t)CB * HWD;
constexpr size_t SZ_TOTAL = OFF_WH1B + (size_t)CB * HWD;

__device__ float g_buf[SZ_TOTAL];
__device__ unsigned g_ctr;

__device__ __forceinline__ float sigm(float x) { return 1.0f / (1.0f + expf(-x)); }

// ---------------- setup: transpose ctx + zero states + seed outputs ----------
__global__ void k_setup(const float* __restrict__ ctx,
                        const float* __restrict__ goal0, const float* __restrict__ w0,
                        float* __restrict__ out) {
    if (blockIdx.x == 0 && threadIdx.x == 0) g_ctr = 0u;
    int idx = blockIdx.x * 256 + threadIdx.x;
    if (idx < CB * CTXD) {
        int b = idx / CTXD, i = idx % CTXD;
        g_buf[OFF_CTXT + (size_t)i * CB + b] = ctx[idx];
        return;
    }
    idx -= CB * CTXD;
    const int R0 = (int)SZ_ZERO;
    const int R2 = CB * DOF;
    const int R3 = CB * WSZ;
    if (idx < R0) {
        g_buf[OFF_ZERO + idx] = 0.f;
    } else if (idx < R0 + R2) {
        int j = idx - R0;
        float v = goal0[j];
        g_buf[OFF_PG + j] = v;
        out[(size_t)(j / DOF) * 20 * DOF + (j % DOF)] = v;   // goals[:,0,:]
    } else if (idx < R0 + R2 + R3) {
        int j = idx - R0 - R2;
        float v = w0[j];
        g_buf[OFF_PW + j] = v;
        out[(size_t)CB * 20 * DOF + (size_t)(j / WSZ) * 20 * WSZ + (j % WSZ)] = v;
    }
}

// ------ transpose bw_W[o][i][j] -> bwT[(j*512+o)][i]  +  tmp_g compute -------
__global__ void k_transb_tmpg(const float* __restrict__ bwW,
                              const float* __restrict__ bgW) {
    if (blockIdx.z == 512) {
        int o = blockIdx.y * 16 + blockIdx.x;
        int b = threadIdx.y * 32 + threadIdx.x;
        float acc[DOF];
#pragma unroll
        for (int j = 0; j < DOF; ++j) acc[j] = 0.f;
        const float* ctxT = &g_buf[OFF_CTXT];
        for (int i = 0; i < CTXD; ++i) {
            float c = ctxT[(size_t)i * CB + b];
            const float* w = &bgW[((size_t)o * CTXD + i) * DOF];
#pragma unroll
            for (int j = 0; j < DOF; ++j) acc[j] = fmaf(c, w[j], acc[j]);
        }
        float* outp = &g_buf[OFF_TMPG + ((size_t)b * PGD + o) * DOF];
#pragma unroll
        for (int j = 0; j < DOF; ++j) outp[j] = acc[j];
        return;
    }
    if (blockIdx.x >= 10) return;
    __shared__ float t[32][33];
    int o = blockIdx.z;
    int j0 = blockIdx.x * 32, i0 = blockIdx.y * 32;
    int tx = threadIdx.x, ty = threadIdx.y;   // 32 x 8
#pragma unroll
    for (int r = 0; r < 32; r += 8) {
        int i = i0 + ty + r, j = j0 + tx;
        float v = (j < ZD) ? bwW[((size_t)o * CTXD + i) * ZD + j] : 0.f;
        t[ty + r][tx] = v;
    }
    __syncthreads();
#pragma unroll
    for (int r = 0; r < 32; r += 8) {
        int j = j0 + ty + r, i = i0 + tx;
        if (j < ZD)
            g_buf[OFF_BWT + ((size_t)j * PWD + o) * CTXD + i] = t[tx][ty + r];
    }
}

// ================= 3xFP16-split mma GEMM-NT tile body ========================
struct Prob {
    const float *A1, *B1; int K1;
    const float *A2, *B2; int K2;     // A2 == nullptr -> single phase
    const float *bias1, *bias2;       // nullable
    float *C;  int ldc;
    float *C2; int ldc2;              // nullable second destination
    int M, N;
    int mode;                         // 0 plain, 1 tanh, 2 lstm
    int H;                            // lstm hidden size
    float *c_st;                      // lstm cell state [b][H] (in/out)
    float *h_out;                     // lstm h output [b][H]
};

#define BM 64
#define BN 64
#define BK 32
#define SH 40                          // half stride per row
#define SMEM_BYTES (4 * BM * SH * 2)   // 20480

__device__ __noinline__ void mma_body(const Prob& p, int bx, int m0,
                                      unsigned char* smraw) {
    __half* sAh = (__half*)smraw;
    __half* sAl = sAh + BM * SH;
    __half* sBh = sAl + BM * SH;
    __half* sBl = sBh + BM * SH;
    float* gates = (float*)smraw;

    int tid  = threadIdx.x;
    int lane = tid & 31;
    int warp = tid >> 5;
    int wm = warp & 3;
    int wn = warp >> 2;

    float acc[4][4];
#pragma unroll
    for (int a = 0; a < 4; ++a)
#pragma unroll
        for (int c = 0; c < 4; ++c) acc[a][c] = 0.f;

    int lr = tid >> 3;                           // 0..31
    int lc = (tid & 7) * 4;

    int n1 = p.K1 / BK;
    int n2 = p.A2 ? (p.K2 / BK) : 0;
    int nIter = n1 + n2;

    float4 ca0, ca1, cb0, cb1, na0, na1, nb0, nb1;

    auto glb = [&](int it, float4& a0, float4& a1, float4& b0, float4& b1) {
        const float *A, *B; int K, kof;
        if (it < n1) { A = p.A1; B = p.B1; K = p.K1; kof = it * BK; }
        else         { A = p.A2; B = p.B2; K = p.K2; kof = (it - n1) * BK; }
        a0 = __ldcg((const float4*)&A[(size_t)(m0 + lr) * K + kof + lc]);
        a1 = __ldcg((const float4*)&A[(size_t)(m0 + lr + 32) * K + kof + lc]);
        int g0, g1;
        if (p.mode == 2) {
            g0 = (lr >> 4) * p.H + bx * 16 + (lr & 15);
            g1 = ((lr + 32) >> 4) * p.H + bx * 16 + (lr & 15);
        } else {
            g0 = bx * BN + lr; g1 = bx * BN + lr + 32;
        }
        b0 = make_float4(0.f, 0.f, 0.f, 0.f); b1 = b0;
        if (p.mode == 2 || g0 < p.N) b0 = *(const float4*)&B[(size_t)g0 * K + kof + lc];
        if (p.mode == 2 || g1 < p.N) b1 = *(const float4*)&B[(size_t)g1 * K + kof + lc];
    };

    auto st4 = [&](__half* h, __half* l, int row, float4 v) {
        __half h0 = __float2half_rn(v.x), h1 = __float2half_rn(v.y);
        __half h2 = __float2half_rn(v.z), h3 = __float2half_rn(v.w);
        __half l0 = __float2half_rn(v.x - __half2float(h0));
        __half l1 = __float2half_rn(v.y - __half2float(h1));
        __half l2 = __float2half_rn(v.z - __half2float(h2));
        __half l3 = __float2half_rn(v.w - __half2float(h3));
        *(__half2*)&h[row * SH + lc]     = __halves2half2(h0, h1);
        *(__half2*)&h[row * SH + lc + 2] = __halves2half2(h2, h3);
        *(__half2*)&l[row * SH + lc]     = __halves2half2(l0, l1);
        *(__half2*)&l[row * SH + lc + 2] = __halves2half2(l2, l3);
    };

    glb(0, ca0, ca1, cb0, cb1);

#pragma unroll 1
    for (int it = 0; it < nIter; ++it) {
        __syncthreads();
        st4(sAh, sAl, lr,      ca0);
        st4(sAh, sAl, lr + 32, ca1);
        st4(sBh, sBl, lr,      cb0);
        st4(sBh, sBl, lr + 32, cb1);
        __syncthreads();
        if (it + 1 < nIter) glb(it + 1, na0, na1, nb0, nb1);

#define MMA16(ACC, AF, BF)                                                       \
    asm volatile(                                                                \
        "mma.sync.aligned.m16n8k16.row.col.f32.f16.f16.f32 "                     \
        "{%0,%1,%2,%3}, {%4,%5,%6,%7}, {%8,%9}, {%0,%1,%2,%3};"                  \
        : "+f"(ACC[0]), "+f"(ACC[1]), "+f"(ACC[2]), "+f"(ACC[3])                 \
        : "r"(AF[0]), "r"(AF[1]), "r"(AF[2]), "r"(AF[3]), "r"(BF[0]), "r"(BF[1]))
#pragma unroll
        for (int kk = 0; kk < BK; kk += 16) {
            int c = kk + (lane & 3) * 2;
            int r = wm * 16 + (lane >> 2);
            unsigned ah[4], al[4];
            ah[0] = *(const unsigned*)&sAh[r * SH + c];
            ah[1] = *(const unsigned*)&sAh[(r + 8) * SH + c];
            ah[2] = *(const unsigned*)&sAh[r * SH + c + 8];
            ah[3] = *(const unsigned*)&sAh[(r + 8) * SH + c + 8];
            al[0] = *(const unsigned*)&sAl[r * SH + c];
            al[1] = *(const unsigned*)&sAl[(r + 8) * SH + c];
            al[2] = *(const unsigned*)&sAl[r * SH + c + 8];
            al[3] = *(const unsigned*)&sAl[(r + 8) * SH + c + 8];
#pragma unroll
            for (int nt = 0; nt < 4; ++nt) {
                int n = wn * 32 + nt * 8 + (lane >> 2);
                unsigned bh[2], bl[2];
                bh[0] = *(const unsigned*)&sBh[n * SH + c];
                bh[1] = *(const unsigned*)&sBh[n * SH + c + 8];
                bl[0] = *(const unsigned*)&sBl[n * SH + c];
                bl[1] = *(const unsigned*)&sBl[n * SH + c + 8];
                MMA16(acc[nt], ah, bl);
                MMA16(acc[nt], al, bh);
                MMA16(acc[nt], ah, bh);
            }
        }
#undef MMA16
        ca0 = na0; ca1 = na1; cb0 = nb0; cb1 = nb1;
    }

    if (p.mode != 2) {
#pragma unroll
        for (int nt = 0; nt < 4; ++nt)
#pragma unroll
            for (int rg = 0; rg < 4; ++rg) {
                int row = m0 + wm * 16 + (lane >> 2) + ((rg >= 2) ? 8 : 0);
                int n = bx * BN + wn * 32 + nt * 8 + (lane & 3) * 2 + (rg & 1);
                if (n < p.N) {
                    float v = acc[nt][rg];
                    if (p.bias1) v += p.bias1[n];
                    if (p.bias2) v += p.bias2[n];
                    if (p.mode == 1) v = tanhf(v);
                    p.C[(size_t)row * p.ldc + n] = v;
                    if (p.C2) p.C2[(size_t)row * p.ldc2 + n] = v;
                }
            }
    } else {
        __syncthreads();
#pragma unroll
        for (int nt = 0; nt < 4; ++nt)
#pragma unroll
            for (int rg = 0; rg < 4; ++rg) {
                int ml = wm * 16 + (lane >> 2) + ((rg >= 2) ? 8 : 0);
                int l = wn * 32 + nt * 8 + (lane & 3) * 2 + (rg & 1);
                gates[((l >> 4) * BM + ml) * 16 + (l & 15)] = acc[nt][rg];
            }
        __syncthreads();
#pragma unroll
        for (int i = tid; i < BM * 16; i += 256) {
            int ml = i >> 4, hl = i & 15;
            int b = m0 + ml;
            int hg = bx * 16 + hl;
            float gi = gates[(0 * BM + ml) * 16 + hl] + p.bias1[0 * p.H + hg] + p.bias2[0 * p.H + hg];
            float gf = gates[(1 * BM + ml) * 16 + hl] + p.bias1[1 * p.H + hg] + p.bias2[1 * p.H + hg];
            float gg = gates[(2 * BM + ml) * 16 + hl] + p.bias1[2 * p.H + hg] + p.bias2[2 * p.H + hg];
            float go = gates[(3 * BM + ml) * 16 + hl] + p.bias1[3 * p.H + hg] + p.bias2[3 * p.H + hg];
            size_t ci = (size_t)b * p.H + hg;
            float c = sigm(gf) * __ldcg(&p.c_st[ci]) + sigm(gi) * tanhf(gg);
            p.c_st[ci] = c;
            p.h_out[ci] = sigm(go) * tanhf(c);
        }
        __syncthreads();   // protect gates smem before next virtual block reuses
    }
}

// standalone GEMM kernel (precompute only)
__global__ __launch_bounds__(256) void k_mma(Prob p0) {
    __shared__ __align__(16) unsigned char smraw[SMEM_BYTES];
    mma_body(p0, blockIdx.x, blockIdx.y * BM, smraw);
}

// ---------------- megakernel pieces ------------------------------------------
__device__ __noinline__ void run_gemm_phase(const Prob& pa, const Prob& pb,
                                            int nva, int nxa, int nvb, int nxb,
                                            unsigned char* smraw) {
    int total = nva + nvb;
    for (int v = blockIdx.x; v < total; v += gridDim.x) {
        bool first = (v < nva);
        const Prob& p = first ? pa : pb;
        int u = first ? v : v - nva;
        int nx = first ? nxa : nxb;
        mma_body(p, u % nx, (u / nx) * BM, smraw);
    }
}

// bilinear body for one batch row b (256 threads)
__device__ __noinline__ void bil_body(int b, const float* bg_b, const float* bw_b,
                                      unsigned char* smraw) {
    float*  zs  = (float*)smraw;              // 306 floats
    float4* red = (float4*)(smraw + 2048);    // 128 float4
    int tid = threadIdx.x;
    __syncthreads();
    for (int j = tid; j < ZD; j += 256)
        zs[j] = (j < DOF) ? __ldcg(&g_buf[OFF_PG + (size_t)b * DOF + j])
                          : __ldcg(&g_buf[OFF_PW + (size_t)b * WSZ + (j - DOF)]);
    __syncthreads();
    int og = tid & 127;
    int jg = tid >> 7;                        // 0..1
    const float4* tw = (const float4*)&g_buf[OFF_TMPW + (size_t)b * NW];
    float4 a0 = make_float4(0.f, 0.f, 0.f, 0.f);
    float4 a1 = a0;
    int j = jg;
#pragma unroll 4
    for (; j + 4 <= ZD; j += 4) {
        float4 v0 = tw[j * 128 + og];
        float4 v1 = tw[(j + 2) * 128 + og];
        float z0 = zs[j], z1 = zs[j + 2];
        a0.x = fmaf(v0.x, z0, a0.x); a0.y = fmaf(v0.y, z0, a0.y);
        a0.z = fmaf(v0.z, z0, a0.z); a0.w = fmaf(v0.w, z0, a0.w);
        a1.x = fmaf(v1.x, z1, a1.x); a1.y = fmaf(v1.y, z1, a1.y);
        a1.z = fmaf(v1.z, z1, a1.z); a1.w = fmaf(v1.w, z1, a1.w);
    }
    for (; j < ZD; j += 2) {
        float4 v0 = tw[j * 128 + og];
        float z0 = zs[j];
        a0.x = fmaf(v0.x, z0, a0.x); a0.y = fmaf(v0.y, z0, a0.y);
        a0.z = fmaf(v0.z, z0, a0.z); a0.w = fmaf(v0.w, z0, a0.w);
    }
    a0.x += a1.x; a0.y += a1.y; a0.z += a1.z; a0.w += a1.w;
    if (jg == 1) red[og] = a0;
    __syncthreads();
    if (jg == 0) {
        float4 r = red[og];
        float4 bb = *(const float4*)&bw_b[og * 4];
        float4 s;
        s.x = a0.x + r.x + bb.x;
        s.y = a0.y + r.y + bb.y;
        s.z = a0.z + r.z + bb.z;
        s.w = a0.w + r.w + bb.w;
        *(float4*)&g_buf[OFF_YPRE + (size_t)b * PWD + og * 4] = s;
    }
    // xpre: o = tid (PGD == 256 threads)
    {
        int o = tid;
        const float* tg = &g_buf[OFF_TMPG + ((size_t)b * PGD + o) * DOF];
        float acc = bg_b[o];
#pragma unroll
        for (int q = 0; q < DOF; ++q) acc = fmaf(tg[q], zs[q], acc);
        g_buf[OFF_XPRE + (size_t)b * PGD + o] = acc;
    }
}

// global software barrier (grid co-resident by construction: 148 blocks)
__device__ __forceinline__ void gbar(unsigned& tgt) {
    __threadfence();                 // release my stores
    __syncthreads();
    tgt += gridDim.x;
    if (threadIdx.x == 0) {
        atomicAdd(&g_ctr, 1u);
        while (*(volatile unsigned*)&g_ctr < tgt) __nanosleep(32);
        __threadfence();             // acquire; invalidates L1 (CCTL.IVALL)
    }
    __syncthreads();
}

// ---------------- persistent 19-step megakernel ------------------------------
__global__ __launch_bounds__(256) void k_loop(
    const float* bg_b, const float* bw_b,
    const float* fcg_W, const float* fcg_b,
    const float* fcw_W, const float* fcw_b,
    const float* lg_Wih, const float* lg_Whh, const float* lg_bih, const float* lg_bhh,
    const float* lw_Wih, const float* lw_Whh, const float* lw_bih, const float* lw_bhh,
    const float* og_W, const float* og_b, const float* ow_W, const float* ow_b,
    float* out)
{
    __shared__ __align__(16) unsigned char smraw[SMEM_BYTES];
    unsigned tgt = 0;
    float* Gb = g_buf;
    float* GH0[2] = {Gb + OFF_GH0A, Gb + OFF_GH0B};
    float* GH1[2] = {Gb + OFF_GH1A, Gb + OFF_GH1B};
    float* WH0[2] = {Gb + OFF_WH0A, Gb + OFF_WH0B};
    float* WH1[2] = {Gb + OFF_WH1A, Gb + OFF_WH1B};

    for (int t = 1; t <= NSTEP; ++t) {
        int ip = (t - 1) & 1, op = t & 1;

        // 1) bilinear phase: 256 virtual blocks (one per batch row)
        for (int v = blockIdx.x; v < CB; v += gridDim.x)
            bil_body(v, bg_b, bw_b, smraw);
        gbar(tgt);

        // 2) fc + tanh: g 16 v-blocks, w 32 v-blocks
        {
            Prob a = {}, b = {};
            a.A1 = Gb + OFF_XPRE; a.B1 = fcg_W; a.K1 = PGD; a.bias1 = fcg_b;
            a.C = Gb + OFF_X; a.ldc = PGD; a.M = CB; a.N = PGD; a.mode = 1;
            b.A1 = Gb + OFF_YPRE; b.B1 = fcw_W; b.K1 = PWD; b.bias1 = fcw_b;
            b.C = Gb + OFF_Y; b.ldc = PWD; b.M = CB; b.N = PWD; b.mode = 1;
            run_gemm_phase(a, b, 16, 4, 32, 8, smraw);
        }
        gbar(tgt);

        // 3) LSTM layer 0: g 64, w 128 v-blocks
        {
            Prob a = {}, b = {};
            a.A1 = Gb + OFF_X;   a.B1 = lg_Wih; a.K1 = PGD;
            a.A2 = GH0[ip];      a.B2 = lg_Whh; a.K2 = HGD;
            a.bias1 = lg_bih;    a.bias2 = lg_bhh;
            a.M = CB; a.mode = 2; a.H = HGD; a.c_st = Gb + OFF_GC0; a.h_out = GH0[op];
            b.A1 = Gb + OFF_Y;   b.B1 = lw_Wih; b.K1 = PWD;
            b.A2 = WH0[ip];      b.B2 = lw_Whh; b.K2 = HWD;
            b.bias1 = lw_bih;    b.bias2 = lw_bhh;
            b.M = CB; b.mode = 2; b.H = HWD; b.c_st = Gb + OFF_WC0; b.h_out = WH0[op];
            run_gemm_phase(a, b, 64, 16, 128, 32, smraw);
        }
        gbar(tgt);

        // 4) LSTM layer 1
        {
            Prob a = {}, b = {};
            a.A1 = GH0[op];      a.B1 = lg_Wih + (size_t)4 * HGD * HGD; a.K1 = HGD;
            a.A2 = GH1[ip];      a.B2 = lg_Whh + (size_t)4 * HGD * HGD; a.K2 = HGD;
            a.bias1 = lg_bih + 4 * HGD; a.bias2 = lg_bhh + 4 * HGD;
            a.M = CB; a.mode = 2; a.H = HGD; a.c_st = Gb + OFF_GC1; a.h_out = GH1[op];
            b.A1 = WH0[op];      b.B1 = lw_Wih + (size_t)4 * HWD * HWD; b.K1 = HWD;
            b.A2 = WH1[ip];      b.B2 = lw_Whh + (size_t)4 * HWD * HWD; b.K2 = HWD;
            b.bias1 = lw_bih + 4 * HWD; b.bias2 = lw_bhh + 4 * HWD;
            b.M = CB; b.mode = 2; b.H = HWD; b.c_st = Gb + OFF_WC1; b.h_out = WH1[op];
            run_gemm_phase(a, b, 64, 16, 128, 32, smraw);
        }
        gbar(tgt);

        // 5) output projections: g 4, w 20 v-blocks
        {
            Prob a = {}, b = {};
            a.A1 = GH1[op]; a.B1 = og_W; a.K1 = HGD; a.bias1 = og_b;
            a.C = out + (size_t)t * DOF; a.ldc = 20 * DOF;
            a.C2 = Gb + OFF_PG; a.ldc2 = DOF;
            a.M = CB; a.N = DOF; a.mode = 0;
            b.A1 = WH1[op]; b.B1 = ow_W; b.K1 = HWD; b.bias1 = ow_b;
            b.C = out + (size_t)CB * 20 * DOF + (size_t)t * WSZ; b.ldc = 20 * WSZ;
            b.C2 = Gb + OFF_PW; b.ldc2 = WSZ;
            b.M = CB; b.N = WSZ; b.mode = 0;
            run_gemm_phase(a, b, 4, 1, 20, 5, smraw);
        }
        gbar(tgt);
    }
}

// ---------------- host: launch sequence ----------------
extern "C" void kernel_launch(void* const* d_in, const int* in_sizes, int n_in,
                              void* d_out, int out_size) {
    const float* ctx    = (const float*)d_in[0];
    const float* goal0  = (const float*)d_in[1];
    const float* w0     = (const float*)d_in[2];
    const float* bg_W   = (const float*)d_in[3];
    const float* bg_b   = (const float*)d_in[4];
    const float* bw_W   = (const float*)d_in[5];
    const float* bw_b   = (const float*)d_in[6];
    const float* fcg_W  = (const float*)d_in[7];
    const float* fcg_b  = (const float*)d_in[8];
    const float* fcw_W  = (const float*)d_in[9];
    const float* fcw_b  = (const float*)d_in[10];
    const float* lg_Wih = (const float*)d_in[11];
    const float* lg_Whh = (const float*)d_in[12];
    const float* lg_bih = (const float*)d_in[13];
    const float* lg_bhh = (const float*)d_in[14];
    const float* lw_Wih = (const float*)d_in[15];
    const float* lw_Whh = (const float*)d_in[16];
    const float* lw_bih = (const float*)d_in[17];
    const float* lw_bhh = (const float*)d_in[18];
    const float* og_W   = (const float*)d_in[19];
    const float* og_b   = (const float*)d_in[20];
    const float* ow_W   = (const float*)d_in[21];
    const float* ow_b   = (const float*)d_in[22];
    float* out = (float*)d_out;

    void* sym = nullptr;
    cudaGetSymbolAddress(&sym, g_buf);
    float* Gb = (float*)sym;

    // ---- precompute (loop-invariant) ----
    int setup_blocks = 512 + (int)((SZ_ZERO + CB * DOF + CB * WSZ + 255) / 256);
    k_setup<<<setup_blocks, 256>>>(ctx, goal0, w0, out);
    k_transb_tmpg<<<dim3(16, 16, 513), dim3(32, 8)>>>(bw_W, bg_W);

    {   // tmp_w = ctx @ bwT^T : M=256, N=156672 (n = j*512+o), K=512
        Prob pc = {};
        pc.A1 = ctx; pc.B1 = Gb + OFF_BWT; pc.K1 = CTXD;
        pc.C = Gb + OFF_TMPW; pc.ldc = NW;
        pc.M = CB; pc.N = NW; pc.mode = 0;
        k_mma<<<dim3(NW / BN, CB / BM), 256>>>(pc);
    }

    // ---- persistent 19-step loop: 148 blocks (one per SM, co-resident) ----
    k_loop<<<148, 256>>>(bg_b, bw_b, fcg_W, fcg_b, fcw_W, fcw_b,
                         lg_Wih, lg_Whh, lg_bih, lg_bhh,
                         lw_Wih, lw_Whh, lw_bih, lw_bhh,
                         og_W, og_b, ow_W, ow_b, out);
}

// round 16
// speedup vs baseline: 1.8579x; 1.8579x over previous
#include <cuda_runtime.h>
#include <cuda_fp16.h>
#include <math.h>

// ---------------- problem constants ----------------
constexpr int CB   = 256;   // batch
constexpr int CTXD = 512;
constexpr int DOF  = 6;
constexpr int WSZ  = 300;
constexpr int PGD  = 256;
constexpr int PWD  = 512;
constexpr int HGD  = 256;
constexpr int HWD  = 512;
constexpr int ZD   = 306;   // DOF + WSZ
constexpr int NSTEP = 19;   // max_segments - 1
constexpr int NW   = PWD * ZD;   // 156672 = big-GEMM N

// ---------------- scratch layout (single __device__ array, no allocs) ----------
constexpr size_t OFF_TMPW = 0;                               // [b][j*512+o]
constexpr size_t SZ_TMPW  = (size_t)CB * NW;
constexpr size_t OFF_BWT  = OFF_TMPW + SZ_TMPW;              // [(j*512+o)][i]
constexpr size_t SZ_BWT   = (size_t)NW * CTXD;
constexpr size_t OFF_TMPG = OFF_BWT + SZ_BWT;
constexpr size_t SZ_TMPG  = (size_t)CB * PGD * DOF;
constexpr size_t OFF_CTXT = OFF_TMPG + SZ_TMPG;
constexpr size_t OFF_PG   = OFF_CTXT + (size_t)CTXD * CB;
constexpr size_t OFF_PW   = OFF_PG + (size_t)CB * DOF;
constexpr size_t OFF_XPRE = OFF_PW + (size_t)CB * WSZ;
constexpr size_t OFF_YPRE = OFF_XPRE + (size_t)CB * PGD;
constexpr size_t OFF_X    = OFF_YPRE + (size_t)CB * PWD;
constexpr size_t OFF_Y    = OFF_X + (size_t)CB * PGD;
// zero-init region (states used as step-1 inputs)
constexpr size_t OFF_ZERO = OFF_Y + (size_t)CB * PWD;
constexpr size_t OFF_GH0A = OFF_ZERO;
constexpr size_t OFF_GH1A = OFF_GH0A + (size_t)CB * HGD;
constexpr size_t OFF_WH0A = OFF_GH1A + (size_t)CB * HGD;
constexpr size_t OFF_WH1A = OFF_WH0A + (size_t)CB * HWD;
constexpr size_t OFF_GC0  = OFF_WH1A + (size_t)CB * HWD;
constexpr size_t OFF_GC1  = OFF_GC0 + (size_t)CB * HGD;
constexpr size_t OFF_WC0  = OFF_GC1 + (size_t)CB * HGD;
constexpr size_t OFF_WC1  = OFF_WC0 + (size_t)CB * HWD;
constexpr size_t SZ_ZERO  = OFF_WC1 + (size_t)CB * HWD - OFF_ZERO;
// double-buffer "B" halves (not zeroed)
constexpr size_t OFF_GH0B = OFF_WC1 + (size_t)CB * HWD;
constexpr size_t OFF_GH1B = OFF_GH0B + (size_t)CB * HGD;
constexpr size_t OFF_WH0B = OFF_GH1B + (size_t)CB * HGD;
constexpr size_t OFF_WH1B = OFF_WH0B + (size_t)CB * HWD;
constexpr size_t SZ_TOTAL = OFF_WH1B + (size_t)CB * HWD;

__device__ float g_buf[SZ_TOTAL];
__device__ unsigned g_ctr;

__device__ __forceinline__ float sigm(float x) { return 1.0f / (1.0f + expf(-x)); }

// 256-thread group barrier (named). gid 0 -> bar 1, gid 1 -> bar 2.
__device__ __forceinline__ void gsync(int gid) {
    asm volatile("bar.sync %0, 256;" :: "r"(gid + 1) : "memory");
}

// ---------------- setup: transpose ctx + zero states + seed outputs ----------
__global__ void k_setup(const float* __restrict__ ctx,
                        const float* __restrict__ goal0, const float* __restrict__ w0,
                        float* __restrict__ out) {
    if (blockIdx.x == 0 && threadIdx.x == 0) g_ctr = 0u;
    int idx = blockIdx.x * 256 + threadIdx.x;
    if (idx < CB * CTXD) {
        int b = idx / CTXD, i = idx % CTXD;
        g_buf[OFF_CTXT + (size_t)i * CB + b] = ctx[idx];
        return;
    }
    idx -= CB * CTXD;
    const int R0 = (int)SZ_ZERO;
    const int R2 = CB * DOF;
    const int R3 = CB * WSZ;
    if (idx < R0) {
        g_buf[OFF_ZERO + idx] = 0.f;
    } else if (idx < R0 + R2) {
        int j = idx - R0;
        float v = goal0[j];
        g_buf[OFF_PG + j] = v;
        out[(size_t)(j / DOF) * 20 * DOF + (j % DOF)] = v;   // goals[:,0,:]
    } else if (idx < R0 + R2 + R3) {
        int j = idx - R0 - R2;
        float v = w0[j];
        g_buf[OFF_PW + j] = v;
        out[(size_t)CB * 20 * DOF + (size_t)(j / WSZ) * 20 * WSZ + (j % WSZ)] = v;
    }
}

// ------ transpose bw_W[o][i][j] -> bwT[(j*512+o)][i]  +  tmp_g compute -------
__global__ void k_transb_tmpg(const float* __restrict__ bwW,
                              const float* __restrict__ bgW) {
    if (blockIdx.z == 512) {
        int o = blockIdx.y * 16 + blockIdx.x;
        int b = threadIdx.y * 32 + threadIdx.x;
        float acc[DOF];
#pragma unroll
        for (int j = 0; j < DOF; ++j) acc[j] = 0.f;
        const float* ctxT = &g_buf[OFF_CTXT];
        for (int i = 0; i < CTXD; ++i) {
            float c = ctxT[(size_t)i * CB + b];
            const float* w = &bgW[((size_t)o * CTXD + i) * DOF];
#pragma unroll
            for (int j = 0; j < DOF; ++j) acc[j] = fmaf(c, w[j], acc[j]);
        }
        float* outp = &g_buf[OFF_TMPG + ((size_t)b * PGD + o) * DOF];
#pragma unroll
        for (int j = 0; j < DOF; ++j) outp[j] = acc[j];
        return;
    }
    if (blockIdx.x >= 10) return;
    __shared__ float t[32][33];
    int o = blockIdx.z;
    int j0 = blockIdx.x * 32, i0 = blockIdx.y * 32;
    int tx = threadIdx.x, ty = threadIdx.y;   // 32 x 8
#pragma unroll
    for (int r = 0; r < 32; r += 8) {
        int i = i0 + ty + r, j = j0 + tx;
        float v = (j < ZD) ? bwW[((size_t)o * CTXD + i) * ZD + j] : 0.f;
        t[ty + r][tx] = v;
    }
    __syncthreads();
#pragma unroll
    for (int r = 0; r < 32; r += 8) {
        int j = j0 + ty + r, i = i0 + tx;
        if (j < ZD)
            g_buf[OFF_BWT + ((size_t)j * PWD + o) * CTXD + i] = t[tx][ty + r];
    }
}

// ================= 3xFP16-split mma GEMM-NT tile body ========================
struct Prob {
    const float *A1, *B1; int K1;
    const float *A2, *B2; int K2;     // A2 == nullptr -> single phase
    const float *bias1, *bias2;       // nullable
    float *C;  int ldc;
    float *C2; int ldc2;              // nullable second destination
    int M, N;
    int mode;                         // 0 plain, 1 tanh, 2 lstm
    int H;                            // lstm hidden size
    float *c_st;                      // lstm cell state [b][H] (in/out)
    float *h_out;                     // lstm h output [b][H]
};

#define BM 64
#define BN 64
#define BK 32
#define SH 40                          // half stride per row
#define SMEM_BYTES (4 * BM * SH * 2)   // 20480

__device__ __forceinline__ void mma_body(const Prob& p, int bx, int m0, int gid,
                                         unsigned char* smraw) {
    __half* sAh = (__half*)smraw;
    __half* sAl = sAh + BM * SH;
    __half* sBh = sAl + BM * SH;
    __half* sBl = sBh + BM * SH;
    float* gates = (float*)smraw;

    int tid  = threadIdx.x & 255;
    int lane = tid & 31;
    int warp = tid >> 5;
    int wm = warp & 3;
    int wn = warp >> 2;

    float acc[4][4];
#pragma unroll
    for (int a = 0; a < 4; ++a)
#pragma unroll
        for (int c = 0; c < 4; ++c) acc[a][c] = 0.f;

    int lr = tid >> 3;                           // 0..31
    int lc = (tid & 7) * 4;

    int n1 = p.K1 / BK;
    int n2 = p.A2 ? (p.K2 / BK) : 0;
    int nIter = n1 + n2;

    float4 ca0, ca1, cb0, cb1, na0, na1, nb0, nb1;

    auto glb = [&](int it, float4& a0, float4& a1, float4& b0, float4& b1) {
        const float *A, *B; int K, kof;
        if (it < n1) { A = p.A1; B = p.B1; K = p.K1; kof = it * BK; }
        else         { A = p.A2; B = p.B2; K = p.K2; kof = (it - n1) * BK; }
        a0 = *(const float4*)&A[(size_t)(m0 + lr) * K + kof + lc];
        a1 = *(const float4*)&A[(size_t)(m0 + lr + 32) * K + kof + lc];
        int g0, g1;
        if (p.mode == 2) {
            g0 = (lr >> 4) * p.H + bx * 16 + (lr & 15);
            g1 = ((lr + 32) >> 4) * p.H + bx * 16 + (lr & 15);
        } else {
            g0 = bx * BN + lr; g1 = bx * BN + lr + 32;
        }
        b0 = make_float4(0.f, 0.f, 0.f, 0.f); b1 = b0;
        if (p.mode == 2 || g0 < p.N) b0 = *(const float4*)&B[(size_t)g0 * K + kof + lc];
        if (p.mode == 2 || g1 < p.N) b1 = *(const float4*)&B[(size_t)g1 * K + kof + lc];
    };

    auto st4 = [&](__half* h, __half* l, int row, float4 v) {
        __half h0 = __float2half_rn(v.x), h1 = __float2half_rn(v.y);
        __half h2 = __float2half_rn(v.z), h3 = __float2half_rn(v.w);
        __half l0 = __float2half_rn(v.x - __half2float(h0));
        __half l1 = __float2half_rn(v.y - __half2float(h1));
        __half l2 = __float2half_rn(v.z - __half2float(h2));
        __half l3 = __float2half_rn(v.w - __half2float(h3));
        *(__half2*)&h[row * SH + lc]     = __halves2half2(h0, h1);
        *(__half2*)&h[row * SH + lc + 2] = __halves2half2(h2, h3);
        *(__half2*)&l[row * SH + lc]     = __halves2half2(l0, l1);
        *(__half2*)&l[row * SH + lc + 2] = __halves2half2(l2, l3);
    };

    glb(0, ca0, ca1, cb0, cb1);

#pragma unroll 1
    for (int it = 0; it < nIter; ++it) {
        gsync(gid);
        st4(sAh, sAl, lr,      ca0);
        st4(sAh, sAl, lr + 32, ca1);
        st4(sBh, sBl, lr,      cb0);
        st4(sBh, sBl, lr + 32, cb1);
        gsync(gid);
        if (it + 1 < nIter) glb(it + 1, na0, na1, nb0, nb1);

#define MMA16(ACC, AF, BF)                                                       \
    asm volatile(                                                                \
        "mma.sync.aligned.m16n8k16.row.col.f32.f16.f16.f32 "                     \
        "{%0,%1,%2,%3}, {%4,%5,%6,%7}, {%8,%9}, {%0,%1,%2,%3};"                  \
        : "+f"(ACC[0]), "+f"(ACC[1]), "+f"(ACC[2]), "+f"(ACC[3])                 \
        : "r"(AF[0]), "r"(AF[1]), "r"(AF[2]), "r"(AF[3]), "r"(BF[0]), "r"(BF[1]))
#pragma unroll
        for (int kk = 0; kk < BK; kk += 16) {
            int c = kk + (lane & 3) * 2;
            int r = wm * 16 + (lane >> 2);
            unsigned ah[4], al[4];
            ah[0] = *(const unsigned*)&sAh[r * SH + c];
            ah[1] = *(const unsigned*)&sAh[(r + 8) * SH + c];
            ah[2] = *(const unsigned*)&sAh[r * SH + c + 8];
            ah[3] = *(const unsigned*)&sAh[(r + 8) * SH + c + 8];
            al[0] = *(const unsigned*)&sAl[r * SH + c];
            al[1] = *(const unsigned*)&sAl[(r + 8) * SH + c];
            al[2] = *(const unsigned*)&sAl[r * SH + c + 8];
            al[3] = *(const unsigned*)&sAl[(r + 8) * SH + c + 8];
#pragma unroll
            for (int nt = 0; nt < 4; ++nt) {
                int n = wn * 32 + nt * 8 + (lane >> 2);
                unsigned bh[2], bl[2];
                bh[0] = *(const unsigned*)&sBh[n * SH + c];
                bh[1] = *(const unsigned*)&sBh[n * SH + c + 8];
                bl[0] = *(const unsigned*)&sBl[n * SH + c];
                bl[1] = *(const unsigned*)&sBl[n * SH + c + 8];
                MMA16(acc[nt], ah, bl);
                MMA16(acc[nt], al, bh);
                MMA16(acc[nt], ah, bh);
            }
        }
#undef MMA16
        ca0 = na0; ca1 = na1; cb0 = nb0; cb1 = nb1;
    }

    if (p.mode != 2) {
#pragma unroll
        for (int nt = 0; nt < 4; ++nt)
#pragma unroll
            for (int rg = 0; rg < 4; ++rg) {
                int row = m0 + wm * 16 + (lane >> 2) + ((rg >= 2) ? 8 : 0);
                int n = bx * BN + wn * 32 + nt * 8 + (lane & 3) * 2 + (rg & 1);
                if (n < p.N) {
                    float v = acc[nt][rg];
                    if (p.bias1) v += p.bias1[n];
                    if (p.bias2) v += p.bias2[n];
                    if (p.mode == 1) v = tanhf(v);
                    p.C[(size_t)row * p.ldc + n] = v;
                    if (p.C2) p.C2[(size_t)row * p.ldc2 + n] = v;
                }
            }
    } else {
        gsync(gid);
#pragma unroll
        for (int nt = 0; nt < 4; ++nt)
#pragma unroll
            for (int rg = 0; rg < 4; ++rg) {
                int ml = wm * 16 + (lane >> 2) + ((rg >= 2) ? 8 : 0);
                int l = wn * 32 + nt * 8 + (lane & 3) * 2 + (rg & 1);
                gates[((l >> 4) * BM + ml) * 16 + (l & 15)] = acc[nt][rg];
            }
        gsync(gid);
#pragma unroll
        for (int i = tid; i < BM * 16; i += 256) {
            int ml = i >> 4, hl = i & 15;
            int b = m0 + ml;
            int hg = bx * 16 + hl;
            float gi = gates[(0 * BM + ml) * 16 + hl] + p.bias1[0 * p.H + hg] + p.bias2[0 * p.H + hg];
            float gf = gates[(1 * BM + ml) * 16 + hl] + p.bias1[1 * p.H + hg] + p.bias2[1 * p.H + hg];
            float gg = gates[(2 * BM + ml) * 16 + hl] + p.bias1[2 * p.H + hg] + p.bias2[2 * p.H + hg];
            float go = gates[(3 * BM + ml) * 16 + hl] + p.bias1[3 * p.H + hg] + p.bias2[3 * p.H + hg];
            size_t ci = (size_t)b * p.H + hg;
            float c = sigm(gf) * p.c_st[ci] + sigm(gi) * tanhf(gg);
            p.c_st[ci] = c;
            p.h_out[ci] = sigm(go) * tanhf(c);
        }
        gsync(gid);   // protect gates smem before next virtual block reuses
    }
}

// standalone GEMM kernel (precompute only; 256 threads = group 0)
__global__ __launch_bounds__(256) void k_mma(Prob p0) {
    __shared__ __align__(16) unsigned char smraw[SMEM_BYTES];
    mma_body(p0, blockIdx.x, blockIdx.y * BM, 0, smraw);
}

// ---------------- megakernel pieces ------------------------------------------
__device__ __forceinline__ void run_gemm_phase(const Prob& pa, const Prob& pb,
                                               int nva, int nxa, int nvb, int nxb,
                                               int gid, unsigned char* smraw,
                                               int worker, int nworkers) {
    int total = nva + nvb;
    for (int v = worker; v < total; v += nworkers) {
        bool first = (v < nva);
        const Prob& p = first ? pa : pb;
        int u = first ? v : v - nva;
        int nx = first ? nxa : nxb;
        mma_body(p, u % nx, (u / nx) * BM, gid, smraw);
    }
}

// bilinear body for one batch row b (256-thread group)
__device__ __forceinline__ void bil_body(int b, const float* bg_b, const float* bw_b,
                                         int gid, unsigned char* smraw) {
    float*  zs  = (float*)smraw;              // 306 floats
    float4* red = (float4*)(smraw + 2048);    // 128 float4
    int tid = threadIdx.x & 255;
    gsync(gid);
    for (int j = tid; j < ZD; j += 256)
        zs[j] = (j < DOF) ? g_buf[OFF_PG + (size_t)b * DOF + j]
                          : g_buf[OFF_PW + (size_t)b * WSZ + (j - DOF)];
    gsync(gid);
    int og = tid & 127;
    int jg = tid >> 7;                        // 0..1
    const float4* tw = (const float4*)&g_buf[OFF_TMPW + (size_t)b * NW];
    float4 a0 = make_float4(0.f, 0.f, 0.f, 0.f);
    float4 a1 = a0;
    int j = jg;
#pragma unroll 4
    for (; j + 4 <= ZD; j += 4) {
        float4 v0 = tw[j * 128 + og];
        float4 v1 = tw[(j + 2) * 128 + og];
        float z0 = zs[j], z1 = zs[j + 2];
        a0.x = fmaf(v0.x, z0, a0.x); a0.y = fmaf(v0.y, z0, a0.y);
        a0.z = fmaf(v0.z, z0, a0.z); a0.w = fmaf(v0.w, z0, a0.w);
        a1.x = fmaf(v1.x, z1, a1.x); a1.y = fmaf(v1.y, z1, a1.y);
        a1.z = fmaf(v1.z, z1, a1.z); a1.w = fmaf(v1.w, z1, a1.w);
    }
    for (; j < ZD; j += 2) {
        float4 v0 = tw[j * 128 + og];
        float z0 = zs[j];
        a0.x = fmaf(v0.x, z0, a0.x); a0.y = fmaf(v0.y, z0, a0.y);
        a0.z = fmaf(v0.z, z0, a0.z); a0.w = fmaf(v0.w, z0, a0.w);
    }
    a0.x += a1.x; a0.y += a1.y; a0.z += a1.z; a0.w += a1.w;
    if (jg == 1) red[og] = a0;
    gsync(gid);
    if (jg == 0) {
        float4 r = red[og];
        float4 bb = *(const float4*)&bw_b[og * 4];
        float4 s;
        s.x = a0.x + r.x + bb.x;
        s.y = a0.y + r.y + bb.y;
        s.z = a0.z + r.z + bb.z;
        s.w = a0.w + r.w + bb.w;
        *(float4*)&g_buf[OFF_YPRE + (size_t)b * PWD + og * 4] = s;
    }
    // xpre: o = tid (PGD == 256 threads)
    {
        int o = tid;
        const float* tg = &g_buf[OFF_TMPG + ((size_t)b * PGD + o) * DOF];
        float acc = bg_b[o];
#pragma unroll
        for (int q = 0; q < DOF; ++q) acc = fmaf(tg[q], zs[q], acc);
        g_buf[OFF_XPRE + (size_t)b * PGD + o] = acc;
    }
}

// global software barrier (grid co-resident by construction: 148 blocks)
__device__ __forceinline__ void gbar(unsigned& tgt) {
    __threadfence();                 // release my stores
    __syncthreads();
    tgt += gridDim.x;
    if (threadIdx.x == 0) {
        atomicAdd(&g_ctr, 1u);
        while (*(volatile unsigned*)&g_ctr < tgt) __nanosleep(32);
        __threadfence();             // acquire; invalidates L1 (CCTL.IVALL)
    }
    __syncthreads();
}

// ---------------- persistent 19-step megakernel ------------------------------
__global__ __launch_bounds__(512, 1) void k_loop(
    const float* bg_b, const float* bw_b,
    const float* fcg_W, const float* fcg_b,
    const float* fcw_W, const float* fcw_b,
    const float* lg_Wih, const float* lg_Whh, const float* lg_bih, const float* lg_bhh,
    const float* lw_Wih, const float* lw_Whh, const float* lw_bih, const float* lw_bhh,
    const float* og_W, const float* og_b, const float* ow_W, const float* ow_b,
    float* out)
{
    __shared__ __align__(16) unsigned char smraw[2 * SMEM_BYTES];   // 40KB
    int gid = threadIdx.x >> 8;                 // 0 or 1
    unsigned char* sm = smraw + (size_t)gid * SMEM_BYTES;
    int worker = blockIdx.x * 2 + gid;
    int nwk = gridDim.x * 2;                    // 296

    unsigned tgt = 0;
    float* Gb = g_buf;
    float* GH0[2] = {Gb + OFF_GH0A, Gb + OFF_GH0B};
    float* GH1[2] = {Gb + OFF_GH1A, Gb + OFF_GH1B};
    float* WH0[2] = {Gb + OFF_WH0A, Gb + OFF_WH0B};
    float* WH1[2] = {Gb + OFF_WH1A, Gb + OFF_WH1B};

    for (int t = 1; t <= NSTEP; ++t) {
        int ip = (t - 1) & 1, op = t & 1;

        // 1) bilinear phase: 256 rows over 296 workers
        for (int v = worker; v < CB; v += nwk)
            bil_body(v, bg_b, bw_b, gid, sm);
        gbar(tgt);

        // 2) fc + tanh: g 16 v-blocks, w 32 v-blocks
        {
            Prob a = {}, b = {};
            a.A1 = Gb + OFF_XPRE; a.B1 = fcg_W; a.K1 = PGD; a.bias1 = fcg_b;
            a.C = Gb + OFF_X; a.ldc = PGD; a.M = CB; a.N = PGD; a.mode = 1;
            b.A1 = Gb + OFF_YPRE; b.B1 = fcw_W; b.K1 = PWD; b.bias1 = fcw_b;
            b.C = Gb + OFF_Y; b.ldc = PWD; b.M = CB; b.N = PWD; b.mode = 1;
            run_gemm_phase(a, b, 16, 4, 32, 8, gid, sm, worker, nwk);
        }
        gbar(tgt);

        // 3) LSTM layer 0: g 64, w 128 v-blocks
        {
            Prob a = {}, b = {};
            a.A1 = Gb + OFF_X;   a.B1 = lg_Wih; a.K1 = PGD;
            a.A2 = GH0[ip];      a.B2 = lg_Whh; a.K2 = HGD;
            a.bias1 = lg_bih;    a.bias2 = lg_bhh;
            a.M = CB; a.mode = 2; a.H = HGD; a.c_st = Gb + OFF_GC0; a.h_out = GH0[op];
            b.A1 = Gb + OFF_Y;   b.B1 = lw_Wih; b.K1 = PWD;
            b.A2 = WH0[ip];      b.B2 = lw_Whh; b.K2 = HWD;
            b.bias1 = lw_bih;    b.bias2 = lw_bhh;
            b.M = CB; b.mode = 2; b.H = HWD; b.c_st = Gb + OFF_WC0; b.h_out = WH0[op];
            run_gemm_phase(a, b, 64, 16, 128, 32, gid, sm, worker, nwk);
        }
        gbar(tgt);

        // 4) LSTM layer 1
        {
            Prob a = {}, b = {};
            a.A1 = GH0[op];      a.B1 = lg_Wih + (size_t)4 * HGD * HGD; a.K1 = HGD;
            a.A2 = GH1[ip];      a.B2 = lg_Whh + (size_t)4 * HGD * HGD; a.K2 = HGD;
            a.bias1 = lg_bih + 4 * HGD; a.bias2 = lg_bhh + 4 * HGD;
            a.M = CB; a.mode = 2; a.H = HGD; a.c_st = Gb + OFF_GC1; a.h_out = GH1[op];
            b.A1 = WH0[op];      b.B1 = lw_Wih + (size_t)4 * HWD * HWD; b.K1 = HWD;
            b.A2 = WH1[ip];      b.B2 = lw_Whh + (size_t)4 * HWD * HWD; b.K2 = HWD;
            b.bias1 = lw_bih + 4 * HWD; b.bias2 = lw_bhh + 4 * HWD;
            b.M = CB; b.mode = 2; b.H = HWD; b.c_st = Gb + OFF_WC1; b.h_out = WH1[op];
            run_gemm_phase(a, b, 64, 16, 128, 32, gid, sm, worker, nwk);
        }
        gbar(tgt);

        // 5) output projections: g 4, w 20 v-blocks
        {
            Prob a = {}, b = {};
            a.A1 = GH1[op]; a.B1 = og_W; a.K1 = HGD; a.bias1 = og_b;
            a.C = out + (size_t)t * DOF; a.ldc = 20 * DOF;
            a.C2 = Gb + OFF_PG; a.ldc2 = DOF;
            a.M = CB; a.N = DOF; a.mode = 0;
            b.A1 = WH1[op]; b.B1 = ow_W; b.K1 = HWD; b.bias1 = ow_b;
            b.C = out + (size_t)CB * 20 * DOF + (size_t)t * WSZ; b.ldc = 20 * WSZ;
            b.C2 = Gb + OFF_PW; b.ldc2 = WSZ;
            b.M = CB; b.N = WSZ; b.mode = 0;
            run_gemm_phase(a, b, 4, 1, 20, 5, gid, sm, worker, nwk);
        }
        gbar(tgt);
    }
}

// ---------------- host: launch sequence ----------------
extern "C" void kernel_launch(void* const* d_in, const int* in_sizes, int n_in,
                              void* d_out, int out_size) {
    const float* ctx    = (const float*)d_in[0];
    const float* goal0  = (const float*)d_in[1];
    const float* w0     = (const float*)d_in[2];
    const float* bg_W   = (const float*)d_in[3];
    const float* bg_b   = (const float*)d_in[4];
    const float* bw_W   = (const float*)d_in[5];
    const float* bw_b   = (const float*)d_in[6];
    const float* fcg_W  = (const float*)d_in[7];
    const float* fcg_b  = (const float*)d_in[8];
    const float* fcw_W  = (const float*)d_in[9];
    const float* fcw_b  = (const float*)d_in[10];
    const float* lg_Wih = (const float*)d_in[11];
    const float* lg_Whh = (const float*)d_in[12];
    const float* lg_bih = (const float*)d_in[13];
    const float* lg_bhh = (const float*)d_in[14];
    const float* lw_Wih = (const float*)d_in[15];
    const float* lw_Whh = (const float*)d_in[16];
    const float* lw_bih = (const float*)d_in[17];
    const float* lw_bhh = (const float*)d_in[18];
    const float* og_W   = (const float*)d_in[19];
    const float* og_b   = (const float*)d_in[20];
    const float* ow_W   = (const float*)d_in[21];
    const float* ow_b   = (const float*)d_in[22];
    float* out = (float*)d_out;

    void* sym = nullptr;
    cudaGetSymbolAddress(&sym, g_buf);
    float* Gb = (float*)sym;

    // ---- precompute (loop-invariant) ----
    int setup_blocks = 512 + (int)((SZ_ZERO + CB * DOF + CB * WSZ + 255) / 256);
    k_setup<<<setup_blocks, 256>>>(ctx, goal0, w0, out);
    k_transb_tmpg<<<dim3(16, 16, 513), dim3(32, 8)>>>(bw_W, bg_W);

    {   // tmp_w = ctx @ bwT^T : M=256, N=156672 (n = j*512+o), K=512
        Prob pc = {};
        pc.A1 = ctx; pc.B1 = Gb + OFF_BWT; pc.K1 = CTXD;
        pc.C = Gb + OFF_TMPW; pc.ldc = NW;
        pc.M = CB; pc.N = NW; pc.mode = 0;
        k_mma<<<dim3(NW / BN, CB / BM), 256>>>(pc);
    }

    // ---- persistent 19-step loop: 148 blocks x 512 threads (2 groups) ----
    k_loop<<<148, 512>>>(bg_b, bw_b, fcg_W, fcg_b, fcw_W, fcw_b,
                         lg_Wih, lg_Whh, lg_bih, lg_bhh,
                         lw_Wih, lw_Whh, lw_bih, lw_bhh,
                         og_W, og_b, ow_W, ow_b, out);
}